// round 9
// baseline (speedup 1.0000x reference)
#include <cuda_runtime.h>

typedef unsigned long long u64;

#define HH    56
#define WW    56
#define CIN   64
#define COUT  64
#define TILE  8

__device__ __forceinline__ u64 addx2(u64 a, u64 b) {
    u64 r; asm("add.rn.f32x2 %0, %1, %2;" : "=l"(r) : "l"(a), "l"(b)); return r;
}
__device__ __forceinline__ u64 pack2(float lo, float hi) {
    u64 r; asm("mov.b64 %0, {%1, %2};" : "=l"(r) : "f"(lo), "f"(hi)); return r;
}
__device__ __forceinline__ void unpack2(u64 v, float& lo, float& hi) {
    asm("mov.b64 {%0, %1}, %2;" : "=f"(lo), "=f"(hi) : "l"(v));
}
__device__ __forceinline__ u64 abs2(u64 v) {   // 2x LOP3 (alu pipe)
    return v & 0x7FFFFFFF7FFFFFFFull;
}

// x pre-paired stride-4: sxp[b][ci][row][t] = (x[t], x[t+4]), t=0..5 (48B rows)
__shared__ __align__(16) u64 sxp_buf[2][8][10][6];   // 2 x 3.84 KB
__shared__ __align__(16) u64 swd_buf[2][8][9][32];   // dup (-w,-w), 2 x 18.4 KB

__device__ __forceinline__ void stage_chunk(
    int buf, int c8, int tid, int tx0, int ty0, int cobase,
    const float* __restrict__ xn, const float* __restrict__ w)
{
    // ---- x chunk: 8 ci x 10 rows x 6 stride-4 pairs (480 items) ----
    #pragma unroll
    for (int it = 0; it < 2; ++it) {
        int idx = it * 256 + tid;
        if (idx < 480) {
            int ci_l = idx / 60;
            int r    = idx - ci_l * 60;
            int row  = r / 6;
            int t    = r - row * 6;
            int gy   = ty0 + row - 1;
            int gx0  = tx0 + t - 1;
            float lo = 0.0f, hi = 0.0f;
            if ((unsigned)gy < (unsigned)HH) {
                const float* base = &xn[((c8 * 8 + ci_l) * HH + gy) * WW];
                if ((unsigned)gx0 < (unsigned)WW)       lo = base[gx0];
                if ((unsigned)(gx0 + 4) < (unsigned)WW) hi = base[gx0 + 4];
            }
            sxp_buf[buf][ci_l][row][t] = pack2(lo, hi);
        }
    }
    // ---- weights: 8 ci x 9 k x 32 co, negated + duplicated (2304 items) ----
    #pragma unroll
    for (int it = 0; it < 9; ++it) {
        int idx  = it * 256 + tid;
        int co   = idx & 31;
        int rest = idx >> 5;                 // 0..71
        int k    = rest % 9;
        int ci_l = rest / 9;
        float wv = -w[((cobase + co) * CIN + c8 * 8 + ci_l) * 9 + k];
        swd_buf[buf][ci_l][k][co] = pack2(wv, wv);
    }
}

// CTA: one n, one 8x8 tile, 32 output channels, 256 threads.
// py = tid&7 (tile row), cg = tid>>3 (0..31) -> ONE output channel.
// Thread: 8 px as 4 stride-4 f32x2 pairs x 1 channel -> 4 u64 accumulators.
__global__ void __launch_bounds__(256, 4)
adder2d_kernel(const float* __restrict__ x,
               const float* __restrict__ w,
               float* __restrict__ out)
{
    const int tid = threadIdx.x;
    const int py  = tid & 7;
    const int cg  = tid >> 3;                // 0..31 -> local co

    const int tx0    = blockIdx.x * TILE;
    const int ty0    = blockIdx.y * TILE;
    const int n      = blockIdx.z >> 1;
    const int cobase = (blockIdx.z & 1) * 32;

    const float* xn = x + (size_t)n * CIN * HH * WW;

    u64 acc0 = 0ull, acc1 = 0ull, acc2 = 0ull, acc3 = 0ull;

    stage_chunk(0, 0, tid, tx0, ty0, cobase, xn, w);

    for (int c8 = 0; c8 < 8; ++c8) {
        const int cb = c8 & 1;
        __syncthreads();   // buf[cb] staged; buf[cb^1] readers done

        if (c8 < 7)
            stage_chunk(cb ^ 1, c8 + 1, tid, tx0, ty0, cobase, xn, w);

        for (int ci_l = 0; ci_l < 8; ++ci_l) {
            #pragma unroll
            for (int kh = 0; kh < 3; ++kh) {
                const ulonglong2* xp =
                    (const ulonglong2*)&sxp_buf[cb][ci_l][py + kh][0];
                ulonglong2 a = xp[0], m = xp[1], e = xp[2];   // 3x LDS.128
                u64 x0 = a.x, x1 = a.y, x2 = m.x, x3 = m.y, x4 = e.x, x5 = e.y;

                #pragma unroll
                for (int kw = 0; kw < 3; ++kw) {
                    u64 p0 = (kw == 0) ? x0 : (kw == 1) ? x1 : x2;
                    u64 p1 = (kw == 0) ? x1 : (kw == 1) ? x2 : x3;
                    u64 p2 = (kw == 0) ? x2 : (kw == 1) ? x3 : x4;
                    u64 p3 = (kw == 0) ? x3 : (kw == 1) ? x4 : x5;
                    // broadcast LDS.64: this thread's channel, dup (-w,-w)
                    u64 w2 = swd_buf[cb][ci_l][kh * 3 + kw][cg];
                    acc0 = addx2(acc0, abs2(addx2(p0, w2)));
                    acc1 = addx2(acc1, abs2(addx2(p1, w2)));
                    acc2 = addx2(acc2, abs2(addx2(p2, w2)));
                    acc3 = addx2(acc3, abs2(addx2(p3, w2)));
                }
            }
        }
    }

    // ---- epilogue: acc_j holds output pixels (j, j+4); out = -sum ----
    float f[8];
    float lo, hi;
    unpack2(acc0, lo, hi); f[0] = -lo; f[4] = -hi;
    unpack2(acc1, lo, hi); f[1] = -lo; f[5] = -hi;
    unpack2(acc2, lo, hi); f[2] = -lo; f[6] = -hi;
    unpack2(acc3, lo, hi); f[3] = -lo; f[7] = -hi;

    float* o = out + (((size_t)n * COUT + cobase + cg) * HH + (ty0 + py)) * WW + tx0;
    ((float4*)o)[0] = make_float4(f[0], f[1], f[2], f[3]);
    ((float4*)o)[1] = make_float4(f[4], f[5], f[6], f[7]);
}

extern "C" void kernel_launch(void* const* d_in, const int* in_sizes, int n_in,
                              void* d_out, int out_size)
{
    const float* x = (const float*)d_in[0];
    const float* w = (const float*)d_in[1];
    float* out     = (float*)d_out;

    dim3 grid(WW / TILE, HH / TILE, 32);   // 7 x 7 x 32 = 1568 CTAs
    adder2d_kernel<<<grid, 256>>>(x, w, out);
}

// round 10
// speedup vs baseline: 1.2126x; 1.2126x over previous
#include <cuda_runtime.h>

typedef unsigned long long u64;

#define HH    56
#define WW    56
#define CIN   64
#define COUT  64
#define TILE  8
#define NB    16
#define QSPLIT 4                       // ci quarters
#define PIX   (NB * COUT * HH * WW)    // floats per partial = 12,845,056

// partial[q][n][co][h][w], positive sums; 4 * 12.85M floats = 51.4 MB scratch
__device__ float g_partial[QSPLIT * PIX];

__device__ __forceinline__ u64 addx2(u64 a, u64 b) {
    u64 r; asm("add.rn.f32x2 %0, %1, %2;" : "=l"(r) : "l"(a), "l"(b)); return r;
}
__device__ __forceinline__ u64 pack2(float lo, float hi) {
    u64 r; asm("mov.b64 %0, {%1, %2};" : "=l"(r) : "f"(lo), "f"(hi)); return r;
}
__device__ __forceinline__ void unpack2(u64 v, float& lo, float& hi) {
    asm("mov.b64 {%0, %1}, %2;" : "=f"(lo), "=f"(hi) : "l"(v));
}
__device__ __forceinline__ u64 abs2(u64 v) {   // 2x LOP3 (alu pipe)
    return v & 0x7FFFFFFF7FFFFFFFull;
}

// x pre-paired stride-4: sxp[ci][row][t] = (x[t], x[t+4]), t=0..5 (48B rows)
__shared__ __align__(16) u64 sxp[8][10][6];     // 3.84 KB
__shared__ __align__(16) u64 swd[8][9][64];     // dup (-w,-w) pairs, 36.9 KB

// CTA: one (n, ci-quarter), one 8x8 tile, ALL 64 output channels.
// 128 threads: py = tid&7, cg = tid>>3 -> 4 channels each.
// Thread: 8 px as 4 stride-4 f32x2 pairs x 4 channels -> 16 u64 acc.
__global__ void __launch_bounds__(128, 5)
adder2d_partial_kernel(const float* __restrict__ x,
                       const float* __restrict__ w)
{
    const int tid  = threadIdx.x;
    const int py   = tid & 7;
    const int co4  = (tid >> 3) * 4;

    const int tx0 = blockIdx.x * TILE;
    const int ty0 = blockIdx.y * TILE;
    const int n   = blockIdx.z >> 2;
    const int q   = blockIdx.z & 3;      // ci quarter: chunks 2q, 2q+1

    const float* xn = x + (size_t)n * CIN * HH * WW;

    u64 acc[4][4];
    #pragma unroll
    for (int c = 0; c < 4; ++c)
        #pragma unroll
        for (int p = 0; p < 4; ++p) acc[c][p] = 0ull;

    for (int cc = 0; cc < 2; ++cc) {
        const int c8 = q * 2 + cc;
        __syncthreads();   // previous chunk's readers done

        // ---- stage x chunk: 8 ci x 10 rows x 6 stride-4 pairs ----
        #pragma unroll
        for (int it = 0; it < 4; ++it) {              // 480 / 128
            int idx = it * 128 + tid;
            if (idx < 480) {
                int ci_l = idx / 60;
                int r    = idx - ci_l * 60;
                int row  = r / 6;
                int t    = r - row * 6;
                int gy   = ty0 + row - 1;
                int gx0  = tx0 + t - 1;
                float lo = 0.0f, hi = 0.0f;
                if ((unsigned)gy < (unsigned)HH) {
                    const float* base = &xn[((c8 * 8 + ci_l) * HH + gy) * WW];
                    if ((unsigned)gx0 < (unsigned)WW)       lo = base[gx0];
                    if ((unsigned)(gx0 + 4) < (unsigned)WW) hi = base[gx0 + 4];
                }
                sxp[ci_l][row][t] = pack2(lo, hi);
            }
        }
        // ---- stage weights: 8 ci x 9 k x 64 co, negated + duplicated ----
        #pragma unroll
        for (int it = 0; it < 36; ++it) {             // 4608 / 128
            int idx  = it * 128 + tid;
            int co   = idx & 63;
            int rest = idx >> 6;                      // 0..71
            int k    = rest % 9;
            int ci_l = rest / 9;
            float wv = -w[(co * CIN + c8 * 8 + ci_l) * 9 + k];
            swd[ci_l][k][co] = pack2(wv, wv);
        }
        __syncthreads();

        for (int ci_l = 0; ci_l < 8; ++ci_l) {
            #pragma unroll
            for (int kh = 0; kh < 3; ++kh) {
                const ulonglong2* xp = (const ulonglong2*)&sxp[ci_l][py + kh][0];
                ulonglong2 a = xp[0], m = xp[1], e = xp[2];
                u64 x0 = a.x, x1 = a.y, x2 = m.x, x3 = m.y, x4 = e.x, x5 = e.y;

                #pragma unroll
                for (int kw = 0; kw < 3; ++kw) {
                    u64 p0 = (kw == 0) ? x0 : (kw == 1) ? x1 : x2;
                    u64 p1 = (kw == 0) ? x1 : (kw == 1) ? x2 : x3;
                    u64 p2 = (kw == 0) ? x2 : (kw == 1) ? x3 : x4;
                    u64 p3 = (kw == 0) ? x3 : (kw == 1) ? x4 : x5;
                    const u64* wrow = &swd[ci_l][kh * 3 + kw][co4];
                    ulonglong2 wA = *(const ulonglong2*)(wrow);
                    ulonglong2 wB = *(const ulonglong2*)(wrow + 2);
                    acc[0][0] = addx2(acc[0][0], abs2(addx2(p0, wA.x)));
                    acc[0][1] = addx2(acc[0][1], abs2(addx2(p1, wA.x)));
                    acc[0][2] = addx2(acc[0][2], abs2(addx2(p2, wA.x)));
                    acc[0][3] = addx2(acc[0][3], abs2(addx2(p3, wA.x)));
                    acc[1][0] = addx2(acc[1][0], abs2(addx2(p0, wA.y)));
                    acc[1][1] = addx2(acc[1][1], abs2(addx2(p1, wA.y)));
                    acc[1][2] = addx2(acc[1][2], abs2(addx2(p2, wA.y)));
                    acc[1][3] = addx2(acc[1][3], abs2(addx2(p3, wA.y)));
                    acc[2][0] = addx2(acc[2][0], abs2(addx2(p0, wB.x)));
                    acc[2][1] = addx2(acc[2][1], abs2(addx2(p1, wB.x)));
                    acc[2][2] = addx2(acc[2][2], abs2(addx2(p2, wB.x)));
                    acc[2][3] = addx2(acc[2][3], abs2(addx2(p3, wB.x)));
                    acc[3][0] = addx2(acc[3][0], abs2(addx2(p0, wB.y)));
                    acc[3][1] = addx2(acc[3][1], abs2(addx2(p1, wB.y)));
                    acc[3][2] = addx2(acc[3][2], abs2(addx2(p2, wB.y)));
                    acc[3][3] = addx2(acc[3][3], abs2(addx2(p3, wB.y)));
                }
            }
        }
    }

    // ---- epilogue: positive partial sums -> scratch[q] ----
    #pragma unroll
    for (int c = 0; c < 4; ++c) {
        float f[8];
        #pragma unroll
        for (int j = 0; j < 4; ++j) {
            float lo, hi;
            unpack2(acc[c][j], lo, hi);
            f[j]     = lo;            // sum|x-w| (negation in reduce)
            f[j + 4] = hi;
        }
        float* o = g_partial + (size_t)q * PIX
                 + (((size_t)n * COUT + co4 + c) * HH + (ty0 + py)) * WW + tx0;
        ((float4*)o)[0] = make_float4(f[0], f[1], f[2], f[3]);
        ((float4*)o)[1] = make_float4(f[4], f[5], f[6], f[7]);
    }
}

// out = -(p0 + p1 + p2 + p3), float4-vectorized
__global__ void __launch_bounds__(256)
adder2d_reduce_kernel(float* __restrict__ out)
{
    const size_t i = (size_t)blockIdx.x * 256 + threadIdx.x;   // float4 index
    const float4* p = (const float4*)g_partial;
    const size_t Q = PIX / 4;                                   // 3,211,264

    float4 a = p[i], b = p[i + Q], c = p[i + 2 * Q], d = p[i + 3 * Q];
    float4 r;
    r.x = -(a.x + b.x + c.x + d.x);
    r.y = -(a.y + b.y + c.y + d.y);
    r.z = -(a.z + b.z + c.z + d.z);
    r.w = -(a.w + b.w + c.w + d.w);
    ((float4*)out)[i] = r;
}

extern "C" void kernel_launch(void* const* d_in, const int* in_sizes, int n_in,
                              void* d_out, int out_size)
{
    const float* x = (const float*)d_in[0];
    const float* w = (const float*)d_in[1];
    float* out     = (float*)d_out;

    dim3 grid(WW / TILE, HH / TILE, NB * QSPLIT);   // 7 x 7 x 64 = 3136 CTAs
    adder2d_partial_kernel<<<grid, 128>>>(x, w);

    adder2d_reduce_kernel<<<PIX / 4 / 256, 256>>>(out);   // 12544 blocks
}